// round 9
// baseline (speedup 1.0000x reference)
#include <cuda_runtime.h>
#include <cuda_bf16.h>
#include <mma.h>
#include <cstdint>

using namespace nvcuda;

#define T_   512
#define B_   128
#define D_   512
#define H_   1024
#define G3H  3072

// ---- gi_gemm tiling (proven, verbatim) ----
#define MT   128
#define NT   64
#define KT   32
#define PADA 40
#define PADB 72

// ---- scan (raw mma.sync) ----
#define NCTA    128
#define NCOLS   8
#define SKT     32
#define NCHUNK  (H_ / SKT)                 // 32
#define A_LD    40
#define APL_ELEMS (B_ * A_LD)              // 5120
#define CHUNK_ELEMS (2 * APL_ELEMS)        // 10240
#define CHUNK_BYTES (CHUNK_ELEMS * 2)      // 20480
#define WH_LD   40
#define WPL_BYTES (H_ * WH_LD * 2)         // 81920 per plane
#define SM_W    0
#define SM_A    (2 * WPL_BYTES)            // 163840
#define SM_CTL  (SM_A + 3 * CHUNK_BYTES)   // 225280
#define SMEM_TOTAL (SM_CTL + 64)
#define NTHREADS 544                        // 16 consumer warps + 1 producer

__device__ __align__(256) float         g_Gi[(long long)T_ * B_ * G3H];
__device__ __align__(256) __nv_bfloat16 g_h[2][NCHUNK * CHUNK_ELEMS];
__device__ int      g_reset_mode;
__device__ unsigned g_bar;

// ---------------------------------------------------------------------------
__global__ void init_kernel(const unsigned char* __restrict__ resets) {
    const unsigned int* w = (const unsigned int*)resets;
    bool i32 = true, f32 = true;
    for (int i = 0; i < 16; i++) {
        unsigned int v = w[i];
        if (v != 0u && v != 1u) i32 = false;
        if (v != 0u && v != 0x3F800000u) f32 = false;
    }
    g_reset_mode = i32 ? 1 : (f32 ? 2 : 0);
    g_bar = 0u;
}

__device__ __forceinline__ bool get_reset_m(const void* r, int idx, int m) {
    if (m == 1) return ((const int*)r)[idx] != 0;
    if (m == 2) return ((const float*)r)[idx] != 0.0f;
    return ((const unsigned char*)r)[idx] != 0;
}

__device__ __forceinline__ void split2(float v, __nv_bfloat16& hi, __nv_bfloat16& lo) {
    hi = __float2bfloat16(v);
    lo = __float2bfloat16(v - __bfloat162float(hi));
}

__device__ __forceinline__ unsigned smem_u32(const void* p) {
    return (unsigned)__cvta_generic_to_shared(p);
}
__device__ __forceinline__ void mbar_init(unsigned a, unsigned c) {
    asm volatile("mbarrier.init.shared.b64 [%0], %1;" :: "r"(a), "r"(c) : "memory");
}
__device__ __forceinline__ void mbar_arrive(unsigned a) {
    asm volatile("mbarrier.arrive.shared.b64 _, [%0];" :: "r"(a) : "memory");
}
__device__ __forceinline__ void mbar_expect_tx(unsigned a, unsigned bytes) {
    asm volatile("mbarrier.arrive.expect_tx.shared.b64 _, [%0], %1;"
                 :: "r"(a), "r"(bytes) : "memory");
}
__device__ __forceinline__ void mbar_wait(unsigned a, unsigned parity) {
    asm volatile(
        "{\n\t.reg .pred P;\n\t"
        "W_%=:\n\t"
        "mbarrier.try_wait.parity.acquire.cta.shared::cta.b64 P, [%0], %1, 0x989680;\n\t"
        "@P bra D_%=;\n\t"
        "bra.uni W_%=;\n\t"
        "D_%=:\n\t}"
        :: "r"(a), "r"(parity) : "memory");
}
__device__ __forceinline__ void bulk_ld(unsigned dst, const void* src,
                                        unsigned bytes, unsigned mbar) {
    asm volatile(
        "cp.async.bulk.shared::cta.global.mbarrier::complete_tx::bytes [%0], [%1], %2, [%3];"
        :: "r"(dst), "l"(src), "r"(bytes), "r"(mbar) : "memory");
}

__device__ __forceinline__ void ldsm_x4(unsigned* r, unsigned a) {
    asm volatile("ldmatrix.sync.aligned.m8n8.x4.shared.b16 {%0,%1,%2,%3}, [%4];"
                 : "=r"(r[0]), "=r"(r[1]), "=r"(r[2]), "=r"(r[3]) : "r"(a));
}
__device__ __forceinline__ void ldsm_x2t(unsigned* r, unsigned a) {
    asm volatile("ldmatrix.sync.aligned.m8n8.x2.trans.shared.b16 {%0,%1}, [%2];"
                 : "=r"(r[0]), "=r"(r[1]) : "r"(a));
}
__device__ __forceinline__ void mma16816(float* c, const unsigned* a, const unsigned* b) {
    asm volatile(
        "mma.sync.aligned.m16n8k16.row.col.f32.bf16.bf16.f32 "
        "{%0,%1,%2,%3}, {%4,%5,%6,%7}, {%8,%9}, {%0,%1,%2,%3};"
        : "+f"(c[0]), "+f"(c[1]), "+f"(c[2]), "+f"(c[3])
        : "r"(a[0]), "r"(a[1]), "r"(a[2]), "r"(a[3]), "r"(b[0]), "r"(b[1]));
}

__device__ __forceinline__ int hoff(int b, int k) {
    return (k >> 5) * CHUNK_ELEMS + b * A_LD + (k & 31);
}

__global__ void prep_h_kernel(const float* __restrict__ h0,
                              const void* __restrict__ resets)
{
    int i = blockIdx.x * 256 + threadIdx.x;
    int b = i >> 10;
    int k = i & 1023;
    float v = get_reset_m(resets, b, g_reset_mode) ? 0.0f : h0[i];
    __nv_bfloat16 h, l; split2(v, h, l);
    int o = hoff(b, k);
    g_h[0][o] = h;
    g_h[0][o + APL_ELEMS] = l;
}

// ---------------------------------------------------------------------------
// Phase B: Gi = X @ Wi + bi  (proven, verbatim)
// ---------------------------------------------------------------------------
__global__ __launch_bounds__(256) void gi_gemm_kernel(
    const float* __restrict__ X,
    const float* __restrict__ Wi,
    const float* __restrict__ bi)
{
    __shared__ __align__(16) __nv_bfloat16 sAh[MT * PADA], sAl[MT * PADA];
    __shared__ __align__(16) __nv_bfloat16 sBh[KT * PADB], sBl[KT * PADB];
    __shared__ __align__(16) float sBias[16 * NT];

    const int n0  = blockIdx.x * NT;
    const long long m0 = (long long)blockIdx.y * MT;
    const int tid  = threadIdx.x;
    const int warp = tid >> 5;
    const int wm   = warp & 3;
    const int wn   = warp >> 2;

    for (int i = tid; i < 16 * NT; i += 256) sBias[i] = bi[n0 + (i % NT)];
    __syncthreads();

    wmma::fragment<wmma::accumulator, 16, 16, 16, float> acc[2][2];
    for (int i = 0; i < 2; i++)
        for (int j = 0; j < 2; j++)
            wmma::load_matrix_sync(acc[i][j], &sBias[wn * 32 + j * 16], NT,
                                   wmma::mem_row_major);

    for (int k0 = 0; k0 < D_; k0 += KT) {
        __syncthreads();
        for (int i = tid; i < MT * KT / 4; i += 256) {
            int r = i >> 3;
            int c = (i & 7) * 4;
            float4 v = *(const float4*)(X + (m0 + r) * D_ + k0 + c);
            float vs[4] = {v.x, v.y, v.z, v.w};
            #pragma unroll
            for (int q = 0; q < 4; q++) {
                __nv_bfloat16 h, l; split2(vs[q], h, l);
                sAh[r * PADA + c + q] = h;
                sAl[r * PADA + c + q] = l;
            }
        }
        for (int i = tid; i < KT * NT / 4; i += 256) {
            int r = i >> 4;
            int c = (i & 15) * 4;
            float4 v = *(const float4*)(Wi + (long long)(k0 + r) * G3H + n0 + c);
            float vs[4] = {v.x, v.y, v.z, v.w};
            #pragma unroll
            for (int q = 0; q < 4; q++) {
                __nv_bfloat16 h, l; split2(vs[q], h, l);
                sBh[r * PADB + c + q] = h;
                sBl[r * PADB + c + q] = l;
            }
        }
        __syncthreads();

        #pragma unroll
        for (int kk = 0; kk < KT; kk += 16) {
            wmma::fragment<wmma::matrix_a, 16, 16, 16, __nv_bfloat16, wmma::row_major> ah[2], al[2];
            wmma::fragment<wmma::matrix_b, 16, 16, 16, __nv_bfloat16, wmma::row_major> bh[2], bl[2];
            #pragma unroll
            for (int i = 0; i < 2; i++) {
                wmma::load_matrix_sync(ah[i], &sAh[(wm * 32 + i * 16) * PADA + kk], PADA);
                wmma::load_matrix_sync(al[i], &sAl[(wm * 32 + i * 16) * PADA + kk], PADA);
            }
            #pragma unroll
            for (int j = 0; j < 2; j++) {
                wmma::load_matrix_sync(bh[j], &sBh[kk * PADB + wn * 32 + j * 16], PADB);
                wmma::load_matrix_sync(bl[j], &sBl[kk * PADB + wn * 32 + j * 16], PADB);
            }
            #pragma unroll
            for (int i = 0; i < 2; i++)
                #pragma unroll
                for (int j = 0; j < 2; j++) {
                    wmma::mma_sync(acc[i][j], al[i], bh[j], acc[i][j]);
                    wmma::mma_sync(acc[i][j], ah[i], bl[j], acc[i][j]);
                    wmma::mma_sync(acc[i][j], ah[i], bh[j], acc[i][j]);
                }
        }
    }

    for (int i = 0; i < 2; i++)
        for (int j = 0; j < 2; j++) {
            float* p = g_Gi + (m0 + wm * 32 + i * 16) * G3H + n0 + wn * 32 + j * 16;
            wmma::store_matrix_sync(p, acc[i][j], G3H, wmma::mem_row_major);
        }
}

// ---------------------------------------------------------------------------
// Persistent scan: 128 CTAs x 544 threads.
// Warps 0-15: MMA consumers; pair (w, w+8) shares m16 tile, splits chunks by
// parity (w<8: even chunks, w>=8: odd). Warp 16: TMA bulk producer.
// Cross-warp split-reduction via SMEM (aliases drained ring), epilogue on 0-7.
// ---------------------------------------------------------------------------
__global__ __launch_bounds__(NTHREADS, 1) void scan_kernel(
    const float* __restrict__ Wh,
    const float* __restrict__ bhn,
    const void*  __restrict__ resets,
    float*       __restrict__ out)
{
    extern __shared__ __align__(128) char sm[];
    __nv_bfloat16* sW = (__nv_bfloat16*)(sm + SM_W);
    const unsigned sW_u32 = smem_u32(sm + SM_W);
    const unsigned sA_u32 = smem_u32(sm + SM_A);
    float* sX = (float*)(sm + SM_A);      // exchange alias: [8][32][13] floats
    const unsigned ctl      = smem_u32(sm + SM_CTL);
    const unsigned mb_full  = ctl;        // 3 x 8B
    const unsigned mb_empty = ctl + 24;   // 3 x 8B

    const int tid = threadIdx.x;
    const int wid = tid >> 5;
    const int lid = tid & 31;
    const int bid = blockIdx.x;
    const int j0  = bid * NCOLS;
    const int rmode = g_reset_mode;

    // ---- load resident Wh slice
    for (int idx = tid; idx < H_ * 24; idx += NTHREADS) {
        int k = idx / 24;
        int c = idx - k * 24;
        float v = Wh[(long long)k * G3H + (c >> 3) * H_ + j0 + (c & 7)];
        __nv_bfloat16 h, l; split2(v, h, l);
        sW[k * WH_LD + c] = h;
        sW[(WPL_BYTES / 2) + k * WH_LD + c] = l;
    }

    if (tid == 0) {
        #pragma unroll
        for (int i = 0; i < 3; i++) {
            mbar_init(mb_full + i * 8, 1);
            mbar_init(mb_empty + i * 8, 8);
        }
    }
    __syncthreads();
    if (tid < 8) {
        #pragma unroll
        for (int i = 0; i < 3; i++) mbar_arrive(mb_empty + i * 8);
    }
    asm volatile("fence.proxy.async;" ::: "memory");
    __syncthreads();

    // per-warp MMA geometry (pair w, w+8 shares tile wm)
    const int wm  = wid & 7;
    const int grp = (wid >> 3) & 1;       // 0: even chunks, 1: odd chunks
    const unsigned a_off = (unsigned)((wm * 16 + (lid & 15)) * 80 + (lid >> 4) * 16);
    const unsigned b_off = (unsigned)((lid & 15) * 80);

    // epilogue coords
    const int r0 = wm * 16 + (lid >> 2);
    const int r1 = r0 + 8;
    const int cj = (lid & 3) * 2;
    const int col = j0 + cj;
    const int hb0 = hoff(r0, col);
    const int hb1 = hoff(r1, col);
    float bj0 = bhn[col], bj1 = bhn[col + 1];

    unsigned ph_empty = 0;   // producer-only state

    for (int t = 0; t < T_; t++) {
        const __nv_bfloat16* hsrc = g_h[t & 1];
        __nv_bfloat16* hdst = g_h[(t + 1) & 1];

        float gh[3][4];

        if (wid == 16) {
            // ---- producer warp
            if (lid == 0) {
                const char* src = (const char*)hsrc;
                for (int kc = 0; kc < NCHUNK; kc++) {
                    int buf = kc - (kc / 3) * 3;
                    mbar_wait(mb_empty + buf * 8, (ph_empty >> buf) & 1u);
                    ph_empty ^= 1u << buf;
                    mbar_expect_tx(mb_full + buf * 8, CHUNK_BYTES);
                    bulk_ld(sA_u32 + buf * CHUNK_BYTES,
                            src + (long long)kc * CHUNK_BYTES,
                            CHUNK_BYTES, mb_full + buf * 8);
                }
            }
        } else {
            // ---- mainloop over this group's chunks: 9 independent chains
            float acc[9][4];
            #pragma unroll
            for (int i = 0; i < 9; i++)
                #pragma unroll
                for (int q = 0; q < 4; q++) acc[i][q] = 0.0f;

            for (int kc = grp; kc < NCHUNK; kc += 2) {
                const int buf = kc - (kc / 3) * 3;
                // closed-form full-bar phase: uses/step per buffer = 11,11,10
                const int n = ((buf < 2) ? t : 0) + kc / 3;
                mbar_wait(mb_full + buf * 8, (unsigned)(n & 1));

                const unsigned aB = sA_u32 + buf * CHUNK_BYTES;
                const unsigned bRow = (unsigned)(kc * 32) * 80u;
                #pragma unroll
                for (int kk = 0; kk < 2; kk++) {
                    unsigned ah[4], al[4];
                    ldsm_x4(ah, aB + a_off + kk * 32);
                    ldsm_x4(al, aB + CHUNK_BYTES / 2 + a_off + kk * 32);
                    unsigned bbase = sW_u32 + bRow + (unsigned)(kk * 16) * 80u + b_off;
                    #pragma unroll
                    for (int tn = 0; tn < 3; tn++) {
                        unsigned bh[2], bl[2];
                        ldsm_x2t(bh, bbase + tn * 16);
                        ldsm_x2t(bl, bbase + tn * 16 + WPL_BYTES);
                        mma16816(acc[tn * 3 + 0], al, bh);
                        mma16816(acc[tn * 3 + 1], ah, bl);
                        mma16816(acc[tn * 3 + 2], ah, bh);
                    }
                }
                if (lid == 0) mbar_arrive(mb_empty + buf * 8);
            }

            // reduce the 3 splits locally
            #pragma unroll
            for (int tn = 0; tn < 3; tn++)
                #pragma unroll
                for (int q = 0; q < 4; q++)
                    gh[tn][q] = acc[tn * 3][q] + acc[tn * 3 + 1][q] + acc[tn * 3 + 2][q];
        }

        // ---- cross-warp reduction: group 1 partials -> SMEM -> group 0 adds
        __syncthreads();   // all chunks consumed; ring buffers free for exchange
        if (wid >= 8 && wid < 16) {
            float* p = sX + ((wid - 8) * 32 + lid) * 13;
            #pragma unroll
            for (int tn = 0; tn < 3; tn++)
                #pragma unroll
                for (int q = 0; q < 4; q++) p[tn * 4 + q] = gh[tn][q];
        }
        __syncthreads();

        if (wid < 8) {
            const float* p = sX + (wid * 32 + lid) * 13;
            #pragma unroll
            for (int tn = 0; tn < 3; tn++)
                #pragma unroll
                for (int q = 0; q < 4; q++) gh[tn][q] += p[tn * 4 + q];

            // ---- epilogue inputs
            const float* gp0 = g_Gi + (long long)t * B_ * G3H + (long long)r0 * G3H + col;
            const float* gp1 = g_Gi + (long long)t * B_ * G3H + (long long)r1 * G3H + col;
            float2 gr0 = __ldcs((const float2*)gp0);
            float2 gz0 = __ldcs((const float2*)(gp0 + H_));
            float2 gn0 = __ldcs((const float2*)(gp0 + 2 * H_));
            float2 gr1 = __ldcs((const float2*)gp1);
            float2 gz1 = __ldcs((const float2*)(gp1 + H_));
            float2 gn1 = __ldcs((const float2*)(gp1 + 2 * H_));
            unsigned hh0 = __ldcg((const unsigned*)(hsrc + hb0));
            unsigned hl0 = __ldcg((const unsigned*)(hsrc + hb0 + APL_ELEMS));
            unsigned hh1 = __ldcg((const unsigned*)(hsrc + hb1));
            unsigned hl1 = __ldcg((const unsigned*)(hsrc + hb1 + APL_ELEMS));
            bool rstA = (t + 1 < T_) ? get_reset_m(resets, (t + 1) * B_ + r0, rmode) : false;
            bool rstB = (t + 1 < T_) ? get_reset_m(resets, (t + 1) * B_ + r1, rmode) : false;

            float hpA0 = __bfloat162float(__ushort_as_bfloat16((unsigned short)hh0))
                       + __bfloat162float(__ushort_as_bfloat16((unsigned short)hl0));
            float hpA1 = __bfloat162float(__ushort_as_bfloat16((unsigned short)(hh0 >> 16)))
                       + __bfloat162float(__ushort_as_bfloat16((unsigned short)(hl0 >> 16)));
            float hpB0 = __bfloat162float(__ushort_as_bfloat16((unsigned short)hh1))
                       + __bfloat162float(__ushort_as_bfloat16((unsigned short)hl1));
            float hpB1 = __bfloat162float(__ushort_as_bfloat16((unsigned short)(hh1 >> 16)))
                       + __bfloat162float(__ushort_as_bfloat16((unsigned short)(hl1 >> 16)));

            float hA0, hA1, hB0, hB1;
            {
                float r = 1.f / (1.f + __expf(-(gr0.x + gh[0][0])));
                float z = 1.f / (1.f + __expf(-(gz0.x + gh[1][0])));
                float n = tanhf(gn0.x + r * (gh[2][0] + bj0));
                hA0 = (1.f - z) * n + z * hpA0;
            }
            {
                float r = 1.f / (1.f + __expf(-(gr0.y + gh[0][1])));
                float z = 1.f / (1.f + __expf(-(gz0.y + gh[1][1])));
                float n = tanhf(gn0.y + r * (gh[2][1] + bj1));
                hA1 = (1.f - z) * n + z * hpA1;
            }
            {
                float r = 1.f / (1.f + __expf(-(gr1.x + gh[0][2])));
                float z = 1.f / (1.f + __expf(-(gz1.x + gh[1][2])));
                float n = tanhf(gn1.x + r * (gh[2][2] + bj0));
                hB0 = (1.f - z) * n + z * hpB0;
            }
            {
                float r = 1.f / (1.f + __expf(-(gr1.y + gh[0][3])));
                float z = 1.f / (1.f + __expf(-(gz1.y + gh[1][3])));
                float n = tanhf(gn1.y + r * (gh[2][3] + bj1));
                hB1 = (1.f - z) * n + z * hpB1;
            }

            float* outp = out + (long long)t * B_ * H_;
            *(float2*)(outp + (long long)r0 * H_ + col) = make_float2(hA0, hA1);
            *(float2*)(outp + (long long)r1 * H_ + col) = make_float2(hB0, hB1);

            if (t + 1 < T_) {
                float mA0 = rstA ? 0.f : hA0, mA1 = rstA ? 0.f : hA1;
                float mB0 = rstB ? 0.f : hB0, mB1 = rstB ? 0.f : hB1;
                __nv_bfloat16 h0a, l0a, h0b, l0b, h1a, l1a, h1b, l1b;
                split2(mA0, h0a, l0a); split2(mA1, h0b, l0b);
                split2(mB0, h1a, l1a); split2(mB1, h1b, l1b);
                *(unsigned*)(hdst + hb0) =
                    (unsigned)__bfloat16_as_ushort(h0a) | ((unsigned)__bfloat16_as_ushort(h0b) << 16);
                *(unsigned*)(hdst + hb0 + APL_ELEMS) =
                    (unsigned)__bfloat16_as_ushort(l0a) | ((unsigned)__bfloat16_as_ushort(l0b) << 16);
                *(unsigned*)(hdst + hb1) =
                    (unsigned)__bfloat16_as_ushort(h1a) | ((unsigned)__bfloat16_as_ushort(h1b) << 16);
                *(unsigned*)(hdst + hb1 + APL_ELEMS) =
                    (unsigned)__bfloat16_as_ushort(l1a) | ((unsigned)__bfloat16_as_ushort(l1b) << 16);
            }
        }

        // ---- grid barrier (proven)
        __threadfence();
        __syncthreads();
        if (tid == 0) {
            atomicAdd(&g_bar, 1u);
            unsigned target = (unsigned)gridDim.x * (unsigned)(t + 1);
            unsigned v;
            do {
                asm volatile("ld.acquire.gpu.u32 %0, [%1];" : "=r"(v) : "l"(&g_bar));
                if (v < target) __nanosleep(32);
            } while (v < target);
        }
        __syncthreads();
    }
}

// ---------------------------------------------------------------------------
extern "C" void kernel_launch(void* const* d_in, const int* in_sizes, int n_in,
                              void* d_out, int out_size)
{
    const float* x      = (const float*)d_in[0];
    const void*  resets = d_in[1];
    const float* h0     = (const float*)d_in[2];
    const float* Wi     = (const float*)d_in[3];
    const float* bi     = (const float*)d_in[4];
    const float* Wh     = (const float*)d_in[5];
    const float* bhn    = (const float*)d_in[6];
    float* out = (float*)d_out;

    cudaFuncSetAttribute(scan_kernel, cudaFuncAttributeMaxDynamicSharedMemorySize,
                         SMEM_TOTAL);

    init_kernel<<<1, 1>>>((const unsigned char*)resets);
    prep_h_kernel<<<(B_ * H_) / 256, 256>>>(h0, resets);
    gi_gemm_kernel<<<dim3(G3H / NT, (T_ * B_) / MT), 256>>>(x, Wi, bi);
    scan_kernel<<<NCTA, NTHREADS, SMEM_TOTAL>>>(Wh, bhn, resets, out);
}

// round 10
// speedup vs baseline: 1.0468x; 1.0468x over previous
#include <cuda_runtime.h>
#include <cuda_bf16.h>
#include <mma.h>
#include <cstdint>

using namespace nvcuda;

#define T_   512
#define B_   128
#define D_   512
#define H_   1024
#define G3H  3072

// ---- gi_gemm tiling (proven, verbatim) ----
#define MT   128
#define NT   64
#define KT   32
#define PADA 40
#define PADB 72

// ---- scan: 2 row-groups x 64 col-groups; CTA = [64 rows x 16 cols] ----
#define NCTA    128
#define RROWS   64                          // batch rows per CTA
#define SKT     32
#define NCHUNK  (H_ / SKT)                  // 32
#define A_LD    40
#define APL_ELEMS (RROWS * A_LD)            // 2560
#define CHUNK_ELEMS (2 * APL_ELEMS)         // 5120 (hi+lo)
#define CHUNK_BYTES (CHUNK_ELEMS * 2)       // 10240
#define HGRP_ELEMS (NCHUNK * CHUNK_ELEMS)   // per row-group, per pingpong
#define B_LD    24                          // 48B rows, conflict-free ldsm
#define BHALF_BYTES (H_ * B_LD * 2)         // 49152
#define BPLANE_BYTES (2 * BHALF_BYTES)      // 98304 (hi plane: 2 halves)
#define SM_W    0
#define SM_A    (2 * BPLANE_BYTES)          // 196608
#define SM_CTL  (SM_A + 3 * CHUNK_BYTES)    // 227328
#define SMEM_TOTAL (SM_CTL + 64)
#define NTHREADS 544                         // 16 consumer warps + 1 producer

__device__ __align__(256) float         g_Gi[(long long)T_ * B_ * G3H];
// h scratch: [pingpong][rowgroup][chunk][plane hi|lo][64][40]
__device__ __align__(256) __nv_bfloat16 g_h[2][2 * HGRP_ELEMS];
__device__ int      g_reset_mode;
__device__ unsigned g_bar;

// ---------------------------------------------------------------------------
__global__ void init_kernel(const unsigned char* __restrict__ resets) {
    const unsigned int* w = (const unsigned int*)resets;
    bool i32 = true, f32 = true;
    for (int i = 0; i < 16; i++) {
        unsigned int v = w[i];
        if (v != 0u && v != 1u) i32 = false;
        if (v != 0u && v != 0x3F800000u) f32 = false;
    }
    g_reset_mode = i32 ? 1 : (f32 ? 2 : 0);
    g_bar = 0u;
}

__device__ __forceinline__ bool get_reset_m(const void* r, int idx, int m) {
    if (m == 1) return ((const int*)r)[idx] != 0;
    if (m == 2) return ((const float*)r)[idx] != 0.0f;
    return ((const unsigned char*)r)[idx] != 0;
}

__device__ __forceinline__ void split2(float v, __nv_bfloat16& hi, __nv_bfloat16& lo) {
    hi = __float2bfloat16(v);
    lo = __float2bfloat16(v - __bfloat162float(hi));
}

__device__ __forceinline__ unsigned smem_u32(const void* p) {
    return (unsigned)__cvta_generic_to_shared(p);
}
__device__ __forceinline__ void mbar_init(unsigned a, unsigned c) {
    asm volatile("mbarrier.init.shared.b64 [%0], %1;" :: "r"(a), "r"(c) : "memory");
}
__device__ __forceinline__ void mbar_arrive(unsigned a) {
    asm volatile("mbarrier.arrive.shared.b64 _, [%0];" :: "r"(a) : "memory");
}
__device__ __forceinline__ void mbar_expect_tx(unsigned a, unsigned bytes) {
    asm volatile("mbarrier.arrive.expect_tx.shared.b64 _, [%0], %1;"
                 :: "r"(a), "r"(bytes) : "memory");
}
__device__ __forceinline__ void mbar_wait(unsigned a, unsigned parity) {
    asm volatile(
        "{\n\t.reg .pred P;\n\t"
        "W_%=:\n\t"
        "mbarrier.try_wait.parity.acquire.cta.shared::cta.b64 P, [%0], %1, 0x989680;\n\t"
        "@P bra D_%=;\n\t"
        "bra.uni W_%=;\n\t"
        "D_%=:\n\t}"
        :: "r"(a), "r"(parity) : "memory");
}
__device__ __forceinline__ void bulk_ld(unsigned dst, const void* src,
                                        unsigned bytes, unsigned mbar) {
    asm volatile(
        "cp.async.bulk.shared::cta.global.mbarrier::complete_tx::bytes [%0], [%1], %2, [%3];"
        :: "r"(dst), "l"(src), "r"(bytes), "r"(mbar) : "memory");
}

__device__ __forceinline__ void ldsm_x4(unsigned* r, unsigned a) {
    asm volatile("ldmatrix.sync.aligned.m8n8.x4.shared.b16 {%0,%1,%2,%3}, [%4];"
                 : "=r"(r[0]), "=r"(r[1]), "=r"(r[2]), "=r"(r[3]) : "r"(a));
}
__device__ __forceinline__ void ldsm_x2t(unsigned* r, unsigned a) {
    asm volatile("ldmatrix.sync.aligned.m8n8.x2.trans.shared.b16 {%0,%1}, [%2];"
                 : "=r"(r[0]), "=r"(r[1]) : "r"(a));
}
__device__ __forceinline__ void mma16816(float* c, const unsigned* a, const unsigned* b) {
    asm volatile(
        "mma.sync.aligned.m16n8k16.row.col.f32.bf16.bf16.f32 "
        "{%0,%1,%2,%3}, {%4,%5,%6,%7}, {%8,%9}, {%0,%1,%2,%3};"
        : "+f"(c[0]), "+f"(c[1]), "+f"(c[2]), "+f"(c[3])
        : "r"(a[0]), "r"(a[1]), "r"(a[2]), "r"(a[3]), "r"(b[0]), "r"(b[1]));
}

__global__ void prep_h_kernel(const float* __restrict__ h0,
                              const void* __restrict__ resets)
{
    int i = blockIdx.x * 256 + threadIdx.x;    // 0 .. B*H-1
    int b = i >> 10;
    int k = i & 1023;
    float v = get_reset_m(resets, b, g_reset_mode) ? 0.0f : h0[i];
    __nv_bfloat16 h, l; split2(v, h, l);
    int rg = b >> 6;
    int r  = b & 63;
    int o = rg * HGRP_ELEMS + (k >> 5) * CHUNK_ELEMS + r * A_LD + (k & 31);
    g_h[0][o] = h;
    g_h[0][o + APL_ELEMS] = l;
}

// ---------------------------------------------------------------------------
// Phase B: Gi = X @ Wi + bi  (proven, verbatim)
// ---------------------------------------------------------------------------
__global__ __launch_bounds__(256) void gi_gemm_kernel(
    const float* __restrict__ X,
    const float* __restrict__ Wi,
    const float* __restrict__ bi)
{
    __shared__ __align__(16) __nv_bfloat16 sAh[MT * PADA], sAl[MT * PADA];
    __shared__ __align__(16) __nv_bfloat16 sBh[KT * PADB], sBl[KT * PADB];
    __shared__ __align__(16) float sBias[16 * NT];

    const int n0  = blockIdx.x * NT;
    const long long m0 = (long long)blockIdx.y * MT;
    const int tid  = threadIdx.x;
    const int warp = tid >> 5;
    const int wm   = warp & 3;
    const int wn   = warp >> 2;

    for (int i = tid; i < 16 * NT; i += 256) sBias[i] = bi[n0 + (i % NT)];
    __syncthreads();

    wmma::fragment<wmma::accumulator, 16, 16, 16, float> acc[2][2];
    for (int i = 0; i < 2; i++)
        for (int j = 0; j < 2; j++)
            wmma::load_matrix_sync(acc[i][j], &sBias[wn * 32 + j * 16], NT,
                                   wmma::mem_row_major);

    for (int k0 = 0; k0 < D_; k0 += KT) {
        __syncthreads();
        for (int i = tid; i < MT * KT / 4; i += 256) {
            int r = i >> 3;
            int c = (i & 7) * 4;
            float4 v = *(const float4*)(X + (m0 + r) * D_ + k0 + c);
            float vs[4] = {v.x, v.y, v.z, v.w};
            #pragma unroll
            for (int q = 0; q < 4; q++) {
                __nv_bfloat16 h, l; split2(vs[q], h, l);
                sAh[r * PADA + c + q] = h;
                sAl[r * PADA + c + q] = l;
            }
        }
        for (int i = tid; i < KT * NT / 4; i += 256) {
            int r = i >> 4;
            int c = (i & 15) * 4;
            float4 v = *(const float4*)(Wi + (long long)(k0 + r) * G3H + n0 + c);
            float vs[4] = {v.x, v.y, v.z, v.w};
            #pragma unroll
            for (int q = 0; q < 4; q++) {
                __nv_bfloat16 h, l; split2(vs[q], h, l);
                sBh[r * PADB + c + q] = h;
                sBl[r * PADB + c + q] = l;
            }
        }
        __syncthreads();

        #pragma unroll
        for (int kk = 0; kk < KT; kk += 16) {
            wmma::fragment<wmma::matrix_a, 16, 16, 16, __nv_bfloat16, wmma::row_major> ah[2], al[2];
            wmma::fragment<wmma::matrix_b, 16, 16, 16, __nv_bfloat16, wmma::row_major> bh[2], bl[2];
            #pragma unroll
            for (int i = 0; i < 2; i++) {
                wmma::load_matrix_sync(ah[i], &sAh[(wm * 32 + i * 16) * PADA + kk], PADA);
                wmma::load_matrix_sync(al[i], &sAl[(wm * 32 + i * 16) * PADA + kk], PADA);
            }
            #pragma unroll
            for (int j = 0; j < 2; j++) {
                wmma::load_matrix_sync(bh[j], &sBh[kk * PADB + wn * 32 + j * 16], PADB);
                wmma::load_matrix_sync(bl[j], &sBl[kk * PADB + wn * 32 + j * 16], PADB);
            }
            #pragma unroll
            for (int i = 0; i < 2; i++)
                #pragma unroll
                for (int j = 0; j < 2; j++) {
                    wmma::mma_sync(acc[i][j], al[i], bh[j], acc[i][j]);
                    wmma::mma_sync(acc[i][j], ah[i], bl[j], acc[i][j]);
                    wmma::mma_sync(acc[i][j], ah[i], bh[j], acc[i][j]);
                }
        }
    }

    for (int i = 0; i < 2; i++)
        for (int j = 0; j < 2; j++) {
            float* p = g_Gi + (m0 + wm * 32 + i * 16) * G3H + n0 + wn * 32 + j * 16;
            wmma::store_matrix_sync(p, acc[i][j], G3H, wmma::mem_row_major);
        }
}

// ---------------------------------------------------------------------------
// Persistent scan: 128 CTAs x 544 threads. CTA = row-group (64 rows) x 16 cols.
// Warps 0-15 consumers: wm=wid&3 (m16 tile), nh=(wid>>2)&1 (8-col half),
// grp=wid>>3 (chunk parity). Warp 16: TMA bulk producer.
// B: 2 halves [1024][24] LD=24 (48B rows, conflict-free), gates packed per
// 8-col block: packed col = gate*8 + (cj&7), half = cj>>3.
// ---------------------------------------------------------------------------
__global__ __launch_bounds__(NTHREADS, 1) void scan_kernel(
    const float* __restrict__ Wh,
    const float* __restrict__ bhn,
    const void*  __restrict__ resets,
    float*       __restrict__ out)
{
    extern __shared__ __align__(128) char sm[];
    __nv_bfloat16* sW = (__nv_bfloat16*)(sm + SM_W);
    const unsigned sW_u32 = smem_u32(sm + SM_W);
    const unsigned sA_u32 = smem_u32(sm + SM_A);
    float* sX = (float*)(sm + SM_A);      // exchange alias: [8][32][13] floats
    const unsigned ctl      = smem_u32(sm + SM_CTL);
    const unsigned mb_full  = ctl;
    const unsigned mb_empty = ctl + 24;

    const int tid = threadIdx.x;
    const int wid = tid >> 5;
    const int lid = tid & 31;
    const int bid = blockIdx.x;
    const int rg  = bid >> 6;             // row group (0/1)
    const int j0  = (bid & 63) * 16;      // 16 hidden cols per CTA
    const int rmode = g_reset_mode;

    // ---- load resident Wh slice: 48 packed cols = 2 halves x (3 gates x 8)
    for (int idx = tid; idx < H_ * 48; idx += NTHREADS) {
        int k = idx / 48;
        int c = idx - k * 48;             // packed col 0..47
        int h = c >= 24;
        int cr = c - h * 24;              // 0..23
        int g  = cr >> 3;
        int cj = cr & 7;
        float v = Wh[(long long)k * G3H + g * H_ + j0 + h * 8 + cj];
        __nv_bfloat16 hh, ll; split2(v, hh, ll);
        int eo = h * (H_ * B_LD) + k * B_LD + cr;   // elems within a plane
        sW[eo] = hh;
        sW[(BPLANE_BYTES / 2) + eo] = ll;
    }

    if (tid == 0) {
        #pragma unroll
        for (int i = 0; i < 3; i++) {
            mbar_init(mb_full + i * 8, 1);
            mbar_init(mb_empty + i * 8, 8);
        }
    }
    __syncthreads();
    if (tid < 8) {
        #pragma unroll
        for (int i = 0; i < 3; i++) mbar_arrive(mb_empty + i * 8);
    }
    asm volatile("fence.proxy.async;" ::: "memory");
    __syncthreads();

    // per-warp MMA geometry
    const int wm  = wid & 3;              // m16 tile (rows wm*16..+16 of 64)
    const int nh  = (wid >> 2) & 1;       // B half (cols j0+nh*8..+8)
    const int grp = (wid >> 3) & 1;       // chunk parity
    const unsigned a_off = (unsigned)((wm * 16 + (lid & 15)) * 80 + (lid >> 4) * 16);
    const unsigned b_half = (unsigned)(nh * BHALF_BYTES);
    const unsigned b_lane = (unsigned)((lid & 15) * 48);

    // epilogue coords (warps 0-7)
    const int r0l = wm * 16 + (lid >> 2);
    const int r1l = r0l + 8;
    const int grow0 = rg * 64 + r0l;
    const int grow1 = rg * 64 + r1l;
    const int col = j0 + nh * 8 + (lid & 3) * 2;
    const int hb0 = (col >> 5) * CHUNK_ELEMS + r0l * A_LD + (col & 31);
    const int hb1 = (col >> 5) * CHUNK_ELEMS + r1l * A_LD + (col & 31);
    float bj0 = bhn[col], bj1 = bhn[col + 1];

    unsigned ph_empty = 0;   // producer-only

    for (int t = 0; t < T_; t++) {
        const __nv_bfloat16* hsrc = g_h[t & 1] + rg * HGRP_ELEMS;
        __nv_bfloat16* hdst = g_h[(t + 1) & 1] + rg * HGRP_ELEMS;

        float gh[3][4];

        if (wid == 16) {
            if (lid == 0) {
                const char* src = (const char*)hsrc;
                for (int kc = 0; kc < NCHUNK; kc++) {
                    int buf = kc - (kc / 3) * 3;
                    mbar_wait(mb_empty + buf * 8, (ph_empty >> buf) & 1u);
                    ph_empty ^= 1u << buf;
                    mbar_expect_tx(mb_full + buf * 8, CHUNK_BYTES);
                    bulk_ld(sA_u32 + buf * CHUNK_BYTES,
                            src + (long long)kc * CHUNK_BYTES,
                            CHUNK_BYTES, mb_full + buf * 8);
                }
            }
        } else {
            float acc[9][4];
            #pragma unroll
            for (int i = 0; i < 9; i++)
                #pragma unroll
                for (int q = 0; q < 4; q++) acc[i][q] = 0.0f;

            for (int kc = grp; kc < NCHUNK; kc += 2) {
                const int buf = kc - (kc / 3) * 3;
                const int n = ((buf < 2) ? t : 0) + kc / 3;   // proven closed form
                mbar_wait(mb_full + buf * 8, (unsigned)(n & 1));

                const unsigned aB = sA_u32 + buf * CHUNK_BYTES;
                #pragma unroll
                for (int kk = 0; kk < 2; kk++) {
                    unsigned ah[4], al[4];
                    ldsm_x4(ah, aB + a_off + kk * 32);
                    ldsm_x4(al, aB + CHUNK_BYTES / 2 + a_off + kk * 32);
                    unsigned bbase = sW_u32 + b_half +
                                     (unsigned)(kc * 32 + kk * 16) * 48u + b_lane;
                    #pragma unroll
                    for (int tn = 0; tn < 3; tn++) {
                        unsigned bh[2], bl[2];
                        ldsm_x2t(bh, bbase + tn * 16);
                        ldsm_x2t(bl, bbase + tn * 16 + BPLANE_BYTES);
                        mma16816(acc[tn * 3 + 0], al, bh);
                        mma16816(acc[tn * 3 + 1], ah, bl);
                        mma16816(acc[tn * 3 + 2], ah, bh);
                    }
                }
                if (lid == 0) mbar_arrive(mb_empty + buf * 8);
            }

            #pragma unroll
            for (int tn = 0; tn < 3; tn++)
                #pragma unroll
                for (int q = 0; q < 4; q++)
                    gh[tn][q] = acc[tn * 3][q] + acc[tn * 3 + 1][q] + acc[tn * 3 + 2][q];
        }

        // ---- cross-warp reduction: grp1 partials -> SMEM -> grp0 adds
        __syncthreads();
        if (wid >= 8 && wid < 16) {
            float* p = sX + ((wid - 8) * 32 + lid) * 13;
            #pragma unroll
            for (int tn = 0; tn < 3; tn++)
                #pragma unroll
                for (int q = 0; q < 4; q++) p[tn * 4 + q] = gh[tn][q];
        }
        __syncthreads();

        if (wid < 8) {
            const float* p = sX + (wid * 32 + lid) * 13;
            #pragma unroll
            for (int tn = 0; tn < 3; tn++)
                #pragma unroll
                for (int q = 0; q < 4; q++) gh[tn][q] += p[tn * 4 + q];

            // ---- epilogue inputs
            const float* gp0 = g_Gi + (long long)t * B_ * G3H + (long long)grow0 * G3H + col;
            const float* gp1 = g_Gi + (long long)t * B_ * G3H + (long long)grow1 * G3H + col;
            float2 gr0 = __ldcs((const float2*)gp0);
            float2 gz0 = __ldcs((const float2*)(gp0 + H_));
            float2 gn0 = __ldcs((const float2*)(gp0 + 2 * H_));
            float2 gr1 = __ldcs((const float2*)gp1);
            float2 gz1 = __ldcs((const float2*)(gp1 + H_));
            float2 gn1 = __ldcs((const float2*)(gp1 + 2 * H_));
            unsigned hh0 = __ldcg((const unsigned*)(hsrc + hb0));
            unsigned hl0 = __ldcg((const unsigned*)(hsrc + hb0 + APL_ELEMS));
            unsigned hh1 = __ldcg((const unsigned*)(hsrc + hb1));
            unsigned hl1 = __ldcg((const unsigned*)(hsrc + hb1 + APL_ELEMS));
            bool rstA = (t + 1 < T_) ? get_reset_m(resets, (t + 1) * B_ + grow0, rmode) : false;
            bool rstB = (t + 1 < T_) ? get_reset_m(resets, (t + 1) * B_ + grow1, rmode) : false;

            float hpA0 = __bfloat162float(__ushort_as_bfloat16((unsigned short)hh0))
                       + __bfloat162float(__ushort_as_bfloat16((unsigned short)hl0));
            float hpA1 = __bfloat162float(__ushort_as_bfloat16((unsigned short)(hh0 >> 16)))
                       + __bfloat162float(__ushort_as_bfloat16((unsigned short)(hl0 >> 16)));
            float hpB0 = __bfloat162float(__ushort_as_bfloat16((unsigned short)hh1))
                       + __bfloat162float(__ushort_as_bfloat16((unsigned short)hl1));
            float hpB1 = __bfloat162float(__ushort_as_bfloat16((unsigned short)(hh1 >> 16)))
                       + __bfloat162float(__ushort_as_bfloat16((unsigned short)(hl1 >> 16)));

            float hA0, hA1, hB0, hB1;
            {
                float r = 1.f / (1.f + __expf(-(gr0.x + gh[0][0])));
                float z = 1.f / (1.f + __expf(-(gz0.x + gh[1][0])));
                float n = tanhf(gn0.x + r * (gh[2][0] + bj0));
                hA0 = (1.f - z) * n + z * hpA0;
            }
            {
                float r = 1.f / (1.f + __expf(-(gr0.y + gh[0][1])));
                float z = 1.f / (1.f + __expf(-(gz0.y + gh[1][1])));
                float n = tanhf(gn0.y + r * (gh[2][1] + bj1));
                hA1 = (1.f - z) * n + z * hpA1;
            }
            {
                float r = 1.f / (1.f + __expf(-(gr1.x + gh[0][2])));
                float z = 1.f / (1.f + __expf(-(gz1.x + gh[1][2])));
                float n = tanhf(gn1.x + r * (gh[2][2] + bj0));
                hB0 = (1.f - z) * n + z * hpB0;
            }
            {
                float r = 1.f / (1.f + __expf(-(gr1.y + gh[0][3])));
                float z = 1.f / (1.f + __expf(-(gz1.y + gh[1][3])));
                float n = tanhf(gn1.y + r * (gh[2][3] + bj1));
                hB1 = (1.f - z) * n + z * hpB1;
            }

            float* outp = out + (long long)t * B_ * H_;
            *(float2*)(outp + (long long)grow0 * H_ + col) = make_float2(hA0, hA1);
            *(float2*)(outp + (long long)grow1 * H_ + col) = make_float2(hB0, hB1);

            if (t + 1 < T_) {
                float mA0 = rstA ? 0.f : hA0, mA1 = rstA ? 0.f : hA1;
                float mB0 = rstB ? 0.f : hB0, mB1 = rstB ? 0.f : hB1;
                __nv_bfloat16 h0a, l0a, h0b, l0b, h1a, l1a, h1b, l1b;
                split2(mA0, h0a, l0a); split2(mA1, h0b, l0b);
                split2(mB0, h1a, l1a); split2(mB1, h1b, l1b);
                *(unsigned*)(hdst + hb0) =
                    (unsigned)__bfloat16_as_ushort(h0a) | ((unsigned)__bfloat16_as_ushort(h0b) << 16);
                *(unsigned*)(hdst + hb0 + APL_ELEMS) =
                    (unsigned)__bfloat16_as_ushort(l0a) | ((unsigned)__bfloat16_as_ushort(l0b) << 16);
                *(unsigned*)(hdst + hb1) =
                    (unsigned)__bfloat16_as_ushort(h1a) | ((unsigned)__bfloat16_as_ushort(h1b) << 16);
                *(unsigned*)(hdst + hb1 + APL_ELEMS) =
                    (unsigned)__bfloat16_as_ushort(l1a) | ((unsigned)__bfloat16_as_ushort(l1b) << 16);
            }
        }

        // ---- grid barrier (proven)
        __threadfence();
        __syncthreads();
        if (tid == 0) {
            atomicAdd(&g_bar, 1u);
            unsigned target = (unsigned)gridDim.x * (unsigned)(t + 1);
            unsigned v;
            do {
                asm volatile("ld.acquire.gpu.u32 %0, [%1];" : "=r"(v) : "l"(&g_bar));
                if (v < target) __nanosleep(32);
            } while (v < target);
        }
        __syncthreads();
    }
}

// ---------------------------------------------------------------------------
extern "C" void kernel_launch(void* const* d_in, const int* in_sizes, int n_in,
                              void* d_out, int out_size)
{
    const float* x      = (const float*)d_in[0];
    const void*  resets = d_in[1];
    const float* h0     = (const float*)d_in[2];
    const float* Wi     = (const float*)d_in[3];
    const float* bi     = (const float*)d_in[4];
    const float* Wh     = (const float*)d_in[5];
    const float* bhn    = (const float*)d_in[6];
    float* out = (float*)d_out;

    cudaFuncSetAttribute(scan_kernel, cudaFuncAttributeMaxDynamicSharedMemorySize,
                         SMEM_TOTAL);

    init_kernel<<<1, 1>>>((const unsigned char*)resets);
    prep_h_kernel<<<(B_ * H_) / 256, 256>>>(h0, resets);
    gi_gemm_kernel<<<dim3(G3H / NT, (T_ * B_) / MT), 256>>>(x, Wi, bi);
    scan_kernel<<<NCTA, NTHREADS, SMEM_TOTAL>>>(Wh, bhn, resets, out);
}